// round 6
// baseline (speedup 1.0000x reference)
#include <cuda_runtime.h>
#include <cstdint>
#include <math.h>

#define MAXN 100000
#define IN_DIM 512

// ---------------- scratch ----------------------------------------------------
__device__ float g_bufA[MAXN * 64];
__device__ float g_bufB[MAXN * 64];
__device__ int   g_rp[MAXN + 1];
__device__ float g_stats[384];        // 3 layers x (64 sum + 64 sumsq)

// ---------------- f32x2 packed FMA (Blackwell FFMA2, PTX-only) ---------------
__device__ __forceinline__ float2 ffma2(float2 a, float2 b, float2 c) {
    unsigned long long ua = *reinterpret_cast<unsigned long long*>(&a);
    unsigned long long ub = *reinterpret_cast<unsigned long long*>(&b);
    unsigned long long uc = *reinterpret_cast<unsigned long long*>(&c);
    unsigned long long ud;
    asm("fma.rn.f32x2 %0, %1, %2, %3;" : "=l"(ud) : "l"(ua), "l"(ub), "l"(uc));
    return *reinterpret_cast<float2*>(&ud);
}

// ---------------- row_ptr (sorted edge_row) + FULL stats zeroing -------------
__global__ void build_rowptr(const int* __restrict__ erow, int E, int n, int* __restrict__ rp) {
    if (blockIdx.x == 0) {
        for (int k = threadIdx.x; k < 384; k += blockDim.x) g_stats[k] = 0.f;
    }
    int i = blockIdx.x * blockDim.x + threadIdx.x;
    if (i > n) return;
    int lo = 0, hi = E;
    while (lo < hi) { int mid = (lo + hi) >> 1; if (erow[mid] < i) lo = mid + 1; else hi = mid; }
    rp[i] = lo;
}

// ---------------- GEMM1: [M,512]x[512,64], 256x64 block, 8x8 thread tile -----
__global__ void __launch_bounds__(256, 2) gemm1_kernel(
    const float* __restrict__ A, const float* __restrict__ B,
    float* __restrict__ C, int M) {
    const int K = 512;
    __shared__ float As[16][260];
    __shared__ float Bs[16][64];

    int tid = threadIdx.x;
    int tm = tid & 31;
    int tn = tid >> 5;
    int rowBase = blockIdx.x * 256;

    float2 acc[8][4];
#pragma unroll
    for (int i = 0; i < 8; ++i)
#pragma unroll
        for (int j = 0; j < 4; ++j) acc[i][j] = make_float2(0.f, 0.f);

    for (int kt = 0; kt < K; kt += 16) {
#pragma unroll
        for (int i = 0; i < 4; ++i) {
            int idx = tid + i * 256;
            int row = idx >> 2, kc = idx & 3;
            int grow = rowBase + row;
            float4 v = make_float4(0.f, 0.f, 0.f, 0.f);
            if (grow < M) v = *(const float4*)(A + (size_t)grow * K + kt + kc * 4);
            As[kc * 4 + 0][row] = v.x;
            As[kc * 4 + 1][row] = v.y;
            As[kc * 4 + 2][row] = v.z;
            As[kc * 4 + 3][row] = v.w;
        }
        {
            int row = tid >> 4, c = (tid & 15) * 4;
            *(float4*)&Bs[row][c] = *(const float4*)(B + (size_t)(kt + row) * 64 + c);
        }
        __syncthreads();

#pragma unroll
        for (int k = 0; k < 16; ++k) {
            float4 alo = *(const float4*)&As[k][tm * 4];
            float4 ahi = *(const float4*)&As[k][128 + tm * 4];
            float2 b2[4];
            *(float4*)&b2[0] = *(const float4*)&Bs[k][tn * 8];
            *(float4*)&b2[2] = *(const float4*)&Bs[k][tn * 8 + 4];
            float alof[4] = {alo.x, alo.y, alo.z, alo.w};
            float ahif[4] = {ahi.x, ahi.y, ahi.z, ahi.w};
#pragma unroll
            for (int i = 0; i < 4; ++i) {
                float2 ad = make_float2(alof[i], alof[i]);
#pragma unroll
                for (int j = 0; j < 4; ++j) acc[i][j] = ffma2(ad, b2[j], acc[i][j]);
            }
#pragma unroll
            for (int i = 0; i < 4; ++i) {
                float2 ad = make_float2(ahif[i], ahif[i]);
#pragma unroll
                for (int j = 0; j < 4; ++j) acc[4 + i][j] = ffma2(ad, b2[j], acc[4 + i][j]);
            }
        }
        __syncthreads();
    }

#pragma unroll
    for (int i = 0; i < 4; ++i) {
        int g0 = rowBase + tm * 4 + i;
        if (g0 < M) {
            float* cp = C + (size_t)g0 * 64 + tn * 8;
            *(float4*)cp       = *(float4*)&acc[i][0];
            *(float4*)(cp + 4) = *(float4*)&acc[i][2];
        }
        int g1 = rowBase + 128 + tm * 4 + i;
        if (g1 < M) {
            float* cp = C + (size_t)g1 * 64 + tn * 8;
            *(float4*)cp       = *(float4*)&acc[4 + i][0];
            *(float4*)(cp + 4) = *(float4*)&acc[4 + i][2];
        }
    }
}

// ---------------- SpMM kernels (float4 gathers, no stats) --------------------
__global__ void __launch_bounds__(256) spmm64(
    const float* __restrict__ sup, const int* __restrict__ ecol,
    const float* __restrict__ ev, const int* __restrict__ rp,
    float* __restrict__ out, int n) {
    int gw = (blockIdx.x * blockDim.x + threadIdx.x) >> 5;
    int lane = threadIdx.x & 31;
    if (gw >= n) return;
    int s = rp[gw], e = rp[gw + 1];
    int h = lane >> 4, sl = (lane & 15) * 4;
    float4 acc = make_float4(0.f, 0.f, 0.f, 0.f);
    int j = s + h;
    for (; j + 2 < e; j += 4) {
        int   c0 = ecol[j],     c1 = ecol[j + 2];
        float v0 = ev[j],       v1 = ev[j + 2];
        float4 r0 = *(const float4*)(sup + (size_t)c0 * 64 + sl);
        float4 r1 = *(const float4*)(sup + (size_t)c1 * 64 + sl);
        acc.x = fmaf(v0, r0.x, acc.x); acc.y = fmaf(v0, r0.y, acc.y);
        acc.z = fmaf(v0, r0.z, acc.z); acc.w = fmaf(v0, r0.w, acc.w);
        acc.x = fmaf(v1, r1.x, acc.x); acc.y = fmaf(v1, r1.y, acc.y);
        acc.z = fmaf(v1, r1.z, acc.z); acc.w = fmaf(v1, r1.w, acc.w);
    }
    for (; j < e; j += 2) {
        int c = ecol[j]; float v = ev[j];
        float4 r = *(const float4*)(sup + (size_t)c * 64 + sl);
        acc.x = fmaf(v, r.x, acc.x); acc.y = fmaf(v, r.y, acc.y);
        acc.z = fmaf(v, r.z, acc.z); acc.w = fmaf(v, r.w, acc.w);
    }
    acc.x += __shfl_down_sync(0xffffffffu, acc.x, 16);
    acc.y += __shfl_down_sync(0xffffffffu, acc.y, 16);
    acc.z += __shfl_down_sync(0xffffffffu, acc.z, 16);
    acc.w += __shfl_down_sync(0xffffffffu, acc.w, 16);
    if (lane < 16) *(float4*)(out + (size_t)gw * 64 + sl) = acc;
}

__global__ void __launch_bounds__(256) spmm32(
    const float* __restrict__ sup, const int* __restrict__ ecol,
    const float* __restrict__ ev, const int* __restrict__ rp,
    float* __restrict__ out, int n) {
    int gw = (blockIdx.x * blockDim.x + threadIdx.x) >> 5;
    int lane = threadIdx.x & 31;
    if (gw >= n) return;
    int s = rp[gw], e = rp[gw + 1];
    int g = lane >> 3, sl = (lane & 7) * 4;
    float4 acc = make_float4(0.f, 0.f, 0.f, 0.f);
    for (int j = s + g; j < e; j += 4) {
        int c = ecol[j]; float v = ev[j];
        float4 r = *(const float4*)(sup + (size_t)c * 32 + sl);
        acc.x = fmaf(v, r.x, acc.x); acc.y = fmaf(v, r.y, acc.y);
        acc.z = fmaf(v, r.z, acc.z); acc.w = fmaf(v, r.w, acc.w);
    }
#pragma unroll
    for (int o = 16; o >= 8; o >>= 1) {
        acc.x += __shfl_down_sync(0xffffffffu, acc.x, o);
        acc.y += __shfl_down_sync(0xffffffffu, acc.y, o);
        acc.z += __shfl_down_sync(0xffffffffu, acc.z, o);
        acc.w += __shfl_down_sync(0xffffffffu, acc.w, o);
    }
    if (lane < 8) *(float4*)(out + (size_t)gw * 32 + sl) = acc;
}

__global__ void __launch_bounds__(256) spmm16(
    const float* __restrict__ sup, const int* __restrict__ ecol,
    const float* __restrict__ ev, const int* __restrict__ rp,
    float* __restrict__ out, int n) {
    int gw = (blockIdx.x * blockDim.x + threadIdx.x) >> 5;
    int lane = threadIdx.x & 31;
    if (gw >= n) return;
    int s = rp[gw], e = rp[gw + 1];
    int g = lane >> 2, sl = (lane & 3) * 4;
    float4 acc = make_float4(0.f, 0.f, 0.f, 0.f);
    for (int j = s + g; j < e; j += 8) {
        int c = ecol[j]; float v = ev[j];
        float4 r = *(const float4*)(sup + (size_t)c * 16 + sl);
        acc.x = fmaf(v, r.x, acc.x); acc.y = fmaf(v, r.y, acc.y);
        acc.z = fmaf(v, r.z, acc.z); acc.w = fmaf(v, r.w, acc.w);
    }
#pragma unroll
    for (int o = 16; o >= 4; o >>= 1) {
        acc.x += __shfl_down_sync(0xffffffffu, acc.x, o);
        acc.y += __shfl_down_sync(0xffffffffu, acc.y, o);
        acc.z += __shfl_down_sync(0xffffffffu, acc.z, o);
        acc.w += __shfl_down_sync(0xffffffffu, acc.w, o);
    }
    if (lane < 4) *(float4*)(out + (size_t)gw * 16 + sl) = acc;
}

// ---------------- column stats: float4 reads, one flush per block ------------
template <int D>
__global__ void __launch_bounds__(256) col_stats(const float* __restrict__ h, int n, int layer) {
    const int S4 = D / 4;
    const int REPS = 256 / S4;
    __shared__ float s_sum[D], s_sq[D];
    int tid = threadIdx.x;
    if (tid < D) { s_sum[tid] = 0.f; s_sq[tid] = 0.f; }
    __syncthreads();
    int ch4 = tid % S4, rep = tid / S4;
    float4 s = make_float4(0.f, 0.f, 0.f, 0.f);
    float4 q = make_float4(0.f, 0.f, 0.f, 0.f);
    for (int r = blockIdx.x * REPS + rep; r < n; r += gridDim.x * REPS) {
        float4 v = *(const float4*)(h + (size_t)r * D + ch4 * 4);
        s.x += v.x; s.y += v.y; s.z += v.z; s.w += v.w;
        q.x = fmaf(v.x, v.x, q.x); q.y = fmaf(v.y, v.y, q.y);
        q.z = fmaf(v.z, v.z, q.z); q.w = fmaf(v.w, v.w, q.w);
    }
    atomicAdd(&s_sum[ch4 * 4 + 0], s.x); atomicAdd(&s_sq[ch4 * 4 + 0], q.x);
    atomicAdd(&s_sum[ch4 * 4 + 1], s.y); atomicAdd(&s_sq[ch4 * 4 + 1], q.y);
    atomicAdd(&s_sum[ch4 * 4 + 2], s.z); atomicAdd(&s_sq[ch4 * 4 + 2], q.z);
    atomicAdd(&s_sum[ch4 * 4 + 3], s.w); atomicAdd(&s_sq[ch4 * 4 + 3], q.w);
    __syncthreads();
    if (tid < D) {
        atomicAdd(&g_stats[layer * 128 + tid], s_sum[tid]);
        atomicAdd(&g_stats[layer * 128 + 64 + tid], s_sq[tid]);
    }
}

// ---------------- persistent fused BN+ELU + small GEMM -----------------------
template <int IN, int OUT>
__global__ void __launch_bounds__(256) gemm_small_fused(
    const float* __restrict__ h, const float* __restrict__ W,
    const float* __restrict__ gamma, const float* __restrict__ beta,
    int layer, float* __restrict__ out, int n) {
    __shared__ float Ws[IN * OUT];
    __shared__ float sc[IN], sh[IN];
    int tid = threadIdx.x;
    for (int i = tid; i < IN * OUT; i += blockDim.x) Ws[i] = W[i];
    if (tid < IN) {
        float invn = 1.0f / (float)n;
        float mean = g_stats[layer * 128 + tid] * invn;
        float var  = g_stats[layer * 128 + 64 + tid] * invn - mean * mean;
        float k    = rsqrtf(var + 1e-5f) * gamma[tid];
        sc[tid] = k;
        sh[tid] = beta[tid] - mean * k;
    }
    __syncthreads();
    int wid = tid >> 5, lane = tid & 31;
    for (int node = blockIdx.x * 8 + wid; node < n; node += gridDim.x * 8) {
        const float* hr = h + (size_t)node * IN;
        float acc0 = 0.f;
#pragma unroll
        for (int k = 0; k < IN; k += 4) {
            float4 h4 = *(const float4*)(hr + k);
            float y0 = fmaf(h4.x, sc[k + 0], sh[k + 0]);
            float y1 = fmaf(h4.y, sc[k + 1], sh[k + 1]);
            float y2 = fmaf(h4.z, sc[k + 2], sh[k + 2]);
            float y3 = fmaf(h4.w, sc[k + 3], sh[k + 3]);
            y0 = y0 > 0.f ? y0 : expm1f(y0);
            y1 = y1 > 0.f ? y1 : expm1f(y1);
            y2 = y2 > 0.f ? y2 : expm1f(y2);
            y3 = y3 > 0.f ? y3 : expm1f(y3);
            acc0 = fmaf(y0, Ws[(k + 0) * OUT + lane], acc0);
            acc0 = fmaf(y1, Ws[(k + 1) * OUT + lane], acc0);
            acc0 = fmaf(y2, Ws[(k + 2) * OUT + lane], acc0);
            acc0 = fmaf(y3, Ws[(k + 3) * OUT + lane], acc0);
        }
        if (lane < OUT) out[(size_t)node * OUT + lane] = acc0;
    }
}

// ---------------- standalone BN+ELU for D=16 (pre layer-4) -------------------
__global__ void bn_elu16(const float* __restrict__ h, float* __restrict__ out,
                         const float* __restrict__ gamma, const float* __restrict__ beta,
                         int n) {
    int i = blockIdx.x * blockDim.x + threadIdx.x;
    if (i >= n * 16) return;
    int ch = i & 15;
    float invn = 1.0f / (float)n;
    float mean = g_stats[256 + ch] * invn;
    float var  = g_stats[256 + 64 + ch] * invn - mean * mean;
    float k = rsqrtf(var + 1e-5f) * gamma[ch];
    float y = fmaf(h[i] - mean, k, beta[ch]);
    out[i] = y > 0.f ? y : expm1f(y);
}

// ---------------- final: [n,16]x[16,40] + log_softmax, persistent ------------
__global__ void __launch_bounds__(256) gemm40_lsm(
    const float* __restrict__ h, const float* __restrict__ W,
    float* __restrict__ out, int n) {
    __shared__ float Ws[16 * 40];
    int tid = threadIdx.x;
    for (int i = tid; i < 16 * 40; i += blockDim.x) Ws[i] = W[i];
    __syncthreads();
    int wid = tid >> 5, lane = tid & 31;
    for (int node = blockIdx.x * 8 + wid; node < n; node += gridDim.x * 8) {
        const float* hr = h + (size_t)node * 16;
        float acc0 = 0.f, acc1 = 0.f;
#pragma unroll
        for (int k = 0; k < 16; k += 4) {
            float4 h4 = *(const float4*)(hr + k);
            acc0 = fmaf(h4.x, Ws[(k + 0) * 40 + lane], acc0);
            acc0 = fmaf(h4.y, Ws[(k + 1) * 40 + lane], acc0);
            acc0 = fmaf(h4.z, Ws[(k + 2) * 40 + lane], acc0);
            acc0 = fmaf(h4.w, Ws[(k + 3) * 40 + lane], acc0);
            if (lane < 8) {
                acc1 = fmaf(h4.x, Ws[(k + 0) * 40 + 32 + lane], acc1);
                acc1 = fmaf(h4.y, Ws[(k + 1) * 40 + 32 + lane], acc1);
                acc1 = fmaf(h4.z, Ws[(k + 2) * 40 + 32 + lane], acc1);
                acc1 = fmaf(h4.w, Ws[(k + 3) * 40 + 32 + lane], acc1);
            }
        }
        float a1 = (lane < 8) ? acc1 : __int_as_float(0xff800000);
        float m = fmaxf(acc0, a1);
#pragma unroll
        for (int o = 16; o; o >>= 1) m = fmaxf(m, __shfl_xor_sync(0xffffffffu, m, o));
        float ssum = expf(acc0 - m) + ((lane < 8) ? expf(acc1 - m) : 0.f);
#pragma unroll
        for (int o = 16; o; o >>= 1) ssum += __shfl_xor_sync(0xffffffffu, ssum, o);
        float lse = logf(ssum) + m;
        out[(size_t)node * 40 + lane] = acc0 - lse;
        if (lane < 8) out[(size_t)node * 40 + 32 + lane] = acc1 - lse;
    }
}

// ---------------- launch ------------------------------------------------------
static inline int dg(long long t, int b) { return (int)((t + b - 1) / b); }

extern "C" void kernel_launch(void* const* d_in, const int* in_sizes, int n_in,
                              void* d_out, int out_size) {
    const float* x    = (const float*)d_in[0];
    const int*   erow = (const int*)d_in[1];
    const int*   ecol = (const int*)d_in[2];
    const float* ev   = (const float*)d_in[3];
    const float* W1   = (const float*)d_in[4];
    const float* W2   = (const float*)d_in[5];
    const float* W3   = (const float*)d_in[6];
    const float* W4   = (const float*)d_in[7];
    const float* g1   = (const float*)d_in[8];
    const float* b1   = (const float*)d_in[9];
    const float* g2   = (const float*)d_in[10];
    const float* b2   = (const float*)d_in[11];
    const float* g3   = (const float*)d_in[12];
    const float* b3   = (const float*)d_in[13];

    int n = in_sizes[0] / IN_DIM;
    int E = in_sizes[1];
    float* out = (float*)d_out;

    float* hA; float* hB; int* rp;
    cudaGetSymbolAddress((void**)&hA, g_bufA);
    cudaGetSymbolAddress((void**)&hB, g_bufB);
    cudaGetSymbolAddress((void**)&rp, g_rp);

    const int TB = 256;
    const int PERS = 1184;     // 8 warps/block persistent grids
    const int STATS_BLOCKS = 592;

    build_rowptr<<<dg(n + 1, TB), TB>>>(erow, E, n, rp);

    // ---- layer 1 ----
    gemm1_kernel<<<dg(n, 256), 256>>>(x, W1, hA, n);
    spmm64<<<dg((long long)n * 32, TB), TB>>>(hA, ecol, ev, rp, hB, n);
    col_stats<64><<<STATS_BLOCKS, 256>>>(hB, n, 0);

    // ---- layer 2 ----
    gemm_small_fused<64, 32><<<PERS, TB>>>(hB, W2, g1, b1, 0, hA, n);
    spmm32<<<dg((long long)n * 32, TB), TB>>>(hA, ecol, ev, rp, hB, n);
    col_stats<32><<<STATS_BLOCKS, 256>>>(hB, n, 1);

    // ---- layer 3 ----
    gemm_small_fused<32, 16><<<PERS, TB>>>(hB, W3, g2, b2, 1, hA, n);
    spmm16<<<dg((long long)n * 32, TB), TB>>>(hA, ecol, ev, rp, hB, n);
    col_stats<16><<<STATS_BLOCKS, 256>>>(hB, n, 2);

    // ---- layer 4 (commuted): bn+elu -> spmm16 -> gemm(16->40)+log_softmax ----
    bn_elu16<<<dg((long long)n * 16, TB), TB>>>(hB, hA, g3, b3, n);
    spmm16<<<dg((long long)n * 32, TB), TB>>>(hA, ecol, ev, rp, hB, n);
    gemm40_lsm<<<PERS, TB>>>(hB, W4, out, n);
}

// round 7
// speedup vs baseline: 1.0050x; 1.0050x over previous
#include <cuda_runtime.h>
#include <cuda_fp16.h>
#include <cstdint>
#include <math.h>

#define MAXN 100000
#define IN_DIM 512

// ---------------- scratch ----------------------------------------------------
__device__ __half g_bufH[MAXN * 64];   // support matrices (gathered operand, fp16)
__device__ float  g_bufF[MAXN * 64];   // spmm outputs (fp32)
__device__ int    g_rp[MAXN + 1];
__device__ float  g_stats[384];        // 3 layers x (64 sum + 64 sumsq)

// ---------------- f32x2 packed FMA (Blackwell FFMA2, PTX-only) ---------------
__device__ __forceinline__ float2 ffma2(float2 a, float2 b, float2 c) {
    unsigned long long ua = *reinterpret_cast<unsigned long long*>(&a);
    unsigned long long ub = *reinterpret_cast<unsigned long long*>(&b);
    unsigned long long uc = *reinterpret_cast<unsigned long long*>(&c);
    unsigned long long ud;
    asm("fma.rn.f32x2 %0, %1, %2, %3;" : "=l"(ud) : "l"(ua), "l"(ub), "l"(uc));
    return *reinterpret_cast<float2*>(&ud);
}

// ---------------- row_ptr (sorted edge_row) + full stats zeroing -------------
__global__ void build_rowptr(const int* __restrict__ erow, int E, int n, int* __restrict__ rp) {
    if (blockIdx.x == 0) {
        for (int k = threadIdx.x; k < 384; k += blockDim.x) g_stats[k] = 0.f;
    }
    int i = blockIdx.x * blockDim.x + threadIdx.x;
    if (i > n) return;
    int lo = 0, hi = E;
    while (lo < hi) { int mid = (lo + hi) >> 1; if (erow[mid] < i) lo = mid + 1; else hi = mid; }
    rp[i] = lo;
}

// ---------------- GEMM1: [M,512]x[512,64] fp32 FFMA2, fp16 output ------------
__global__ void __launch_bounds__(256, 2) gemm1_kernel(
    const float* __restrict__ A, const float* __restrict__ B,
    __half* __restrict__ C, int M) {
    const int K = 512;
    __shared__ float As[16][260];
    __shared__ float Bs[16][64];

    int tid = threadIdx.x;
    int tm = tid & 31;
    int tn = tid >> 5;
    int rowBase = blockIdx.x * 256;

    float2 acc[8][4];
#pragma unroll
    for (int i = 0; i < 8; ++i)
#pragma unroll
        for (int j = 0; j < 4; ++j) acc[i][j] = make_float2(0.f, 0.f);

    for (int kt = 0; kt < K; kt += 16) {
#pragma unroll
        for (int i = 0; i < 4; ++i) {
            int idx = tid + i * 256;
            int row = idx >> 2, kc = idx & 3;
            int grow = rowBase + row;
            float4 v = make_float4(0.f, 0.f, 0.f, 0.f);
            if (grow < M) v = *(const float4*)(A + (size_t)grow * K + kt + kc * 4);
            As[kc * 4 + 0][row] = v.x;
            As[kc * 4 + 1][row] = v.y;
            As[kc * 4 + 2][row] = v.z;
            As[kc * 4 + 3][row] = v.w;
        }
        {
            int row = tid >> 4, c = (tid & 15) * 4;
            *(float4*)&Bs[row][c] = *(const float4*)(B + (size_t)(kt + row) * 64 + c);
        }
        __syncthreads();

#pragma unroll
        for (int k = 0; k < 16; ++k) {
            float4 alo = *(const float4*)&As[k][tm * 4];
            float4 ahi = *(const float4*)&As[k][128 + tm * 4];
            float2 b2[4];
            *(float4*)&b2[0] = *(const float4*)&Bs[k][tn * 8];
            *(float4*)&b2[2] = *(const float4*)&Bs[k][tn * 8 + 4];
            float alof[4] = {alo.x, alo.y, alo.z, alo.w};
            float ahif[4] = {ahi.x, ahi.y, ahi.z, ahi.w};
#pragma unroll
            for (int i = 0; i < 4; ++i) {
                float2 ad = make_float2(alof[i], alof[i]);
#pragma unroll
                for (int j = 0; j < 4; ++j) acc[i][j] = ffma2(ad, b2[j], acc[i][j]);
            }
#pragma unroll
            for (int i = 0; i < 4; ++i) {
                float2 ad = make_float2(ahif[i], ahif[i]);
#pragma unroll
                for (int j = 0; j < 4; ++j) acc[4 + i][j] = ffma2(ad, b2[j], acc[4 + i][j]);
            }
        }
        __syncthreads();
    }

#pragma unroll
    for (int i = 0; i < 4; ++i) {
        int g0 = rowBase + tm * 4 + i;
        if (g0 < M) {
            __half2 hh[4];
#pragma unroll
            for (int j = 0; j < 4; ++j) hh[j] = __floats2half2_rn(acc[i][j].x, acc[i][j].y);
            *(uint4*)(C + (size_t)g0 * 64 + tn * 8) = *(uint4*)hh;
        }
        int g1 = rowBase + 128 + tm * 4 + i;
        if (g1 < M) {
            __half2 hh[4];
#pragma unroll
            for (int j = 0; j < 4; ++j) hh[j] = __floats2half2_rn(acc[4 + i][j].x, acc[4 + i][j].y);
            *(uint4*)(C + (size_t)g1 * 64 + tn * 8) = *(uint4*)hh;
        }
    }
}

// ---------------- fp16 gather helper ----------------------------------------
__device__ __forceinline__ void fma_half8(float* acc, uint4 raw, float v) {
    float2 f;
    f = __half22float2(*(__half2*)&raw.x); acc[0] = fmaf(v, f.x, acc[0]); acc[1] = fmaf(v, f.y, acc[1]);
    f = __half22float2(*(((__half2*)&raw.x) + 1)); acc[2] = fmaf(v, f.x, acc[2]); acc[3] = fmaf(v, f.y, acc[3]);
    f = __half22float2(*(__half2*)&raw.z); acc[4] = fmaf(v, f.x, acc[4]); acc[5] = fmaf(v, f.y, acc[5]);
    f = __half22float2(*(((__half2*)&raw.z) + 1)); acc[6] = fmaf(v, f.x, acc[6]); acc[7] = fmaf(v, f.y, acc[7]);
}

// ---------------- SpMM: half supports, float outputs -------------------------
// D=64: 8-lane groups, each lane covers 8 channels (16B), 4 edges in flight.
__global__ void __launch_bounds__(256) spmm64h(
    const __half* __restrict__ sup, const int* __restrict__ ecol,
    const float* __restrict__ ev, const int* __restrict__ rp,
    float* __restrict__ out, int n) {
    int gw = (blockIdx.x * blockDim.x + threadIdx.x) >> 5;
    int lane = threadIdx.x & 31;
    if (gw >= n) return;
    int s = rp[gw], e = rp[gw + 1];
    int g = lane >> 3, sl = lane & 7;
    float acc[8] = {0.f, 0.f, 0.f, 0.f, 0.f, 0.f, 0.f, 0.f};
    for (int j = s + g; j < e; j += 4) {
        int c = ecol[j]; float v = ev[j];
        uint4 raw = *(const uint4*)(sup + (size_t)c * 64 + sl * 8);
        fma_half8(acc, raw, v);
    }
#pragma unroll
    for (int o = 16; o >= 8; o >>= 1)
#pragma unroll
        for (int i = 0; i < 8; ++i) acc[i] += __shfl_down_sync(0xffffffffu, acc[i], o);
    if (lane < 8) {
        float* op = out + (size_t)gw * 64 + lane * 8;
        *(float4*)op       = make_float4(acc[0], acc[1], acc[2], acc[3]);
        *(float4*)(op + 4) = make_float4(acc[4], acc[5], acc[6], acc[7]);
    }
}

// D=32: 4-lane groups, 8 edges in flight.
__global__ void __launch_bounds__(256) spmm32h(
    const __half* __restrict__ sup, const int* __restrict__ ecol,
    const float* __restrict__ ev, const int* __restrict__ rp,
    float* __restrict__ out, int n) {
    int gw = (blockIdx.x * blockDim.x + threadIdx.x) >> 5;
    int lane = threadIdx.x & 31;
    if (gw >= n) return;
    int s = rp[gw], e = rp[gw + 1];
    int g = lane >> 2, sl = lane & 3;
    float acc[8] = {0.f, 0.f, 0.f, 0.f, 0.f, 0.f, 0.f, 0.f};
    for (int j = s + g; j < e; j += 8) {
        int c = ecol[j]; float v = ev[j];
        uint4 raw = *(const uint4*)(sup + (size_t)c * 32 + sl * 8);
        fma_half8(acc, raw, v);
    }
#pragma unroll
    for (int o = 16; o >= 4; o >>= 1)
#pragma unroll
        for (int i = 0; i < 8; ++i) acc[i] += __shfl_down_sync(0xffffffffu, acc[i], o);
    if (lane < 4) {
        float* op = out + (size_t)gw * 32 + lane * 8;
        *(float4*)op       = make_float4(acc[0], acc[1], acc[2], acc[3]);
        *(float4*)(op + 4) = make_float4(acc[4], acc[5], acc[6], acc[7]);
    }
}

// D=16: 2-lane groups, 16 edges in flight.
__global__ void __launch_bounds__(256) spmm16h(
    const __half* __restrict__ sup, const int* __restrict__ ecol,
    const float* __restrict__ ev, const int* __restrict__ rp,
    float* __restrict__ out, int n) {
    int gw = (blockIdx.x * blockDim.x + threadIdx.x) >> 5;
    int lane = threadIdx.x & 31;
    if (gw >= n) return;
    int s = rp[gw], e = rp[gw + 1];
    int g = lane >> 1, sl = lane & 1;
    float acc[8] = {0.f, 0.f, 0.f, 0.f, 0.f, 0.f, 0.f, 0.f};
    for (int j = s + g; j < e; j += 16) {
        int c = ecol[j]; float v = ev[j];
        uint4 raw = *(const uint4*)(sup + (size_t)c * 16 + sl * 8);
        fma_half8(acc, raw, v);
    }
#pragma unroll
    for (int o = 16; o >= 2; o >>= 1)
#pragma unroll
        for (int i = 0; i < 8; ++i) acc[i] += __shfl_down_sync(0xffffffffu, acc[i], o);
    if (lane < 2) {
        float* op = out + (size_t)gw * 16 + lane * 8;
        *(float4*)op       = make_float4(acc[0], acc[1], acc[2], acc[3]);
        *(float4*)(op + 4) = make_float4(acc[4], acc[5], acc[6], acc[7]);
    }
}

// ---------------- column stats: float4 reads, one flush per block ------------
template <int D>
__global__ void __launch_bounds__(256) col_stats(const float* __restrict__ h, int n, int layer) {
    const int S4 = D / 4;
    const int REPS = 256 / S4;
    __shared__ float s_sum[D], s_sq[D];
    int tid = threadIdx.x;
    if (tid < D) { s_sum[tid] = 0.f; s_sq[tid] = 0.f; }
    __syncthreads();
    int ch4 = tid % S4, rep = tid / S4;
    float4 s = make_float4(0.f, 0.f, 0.f, 0.f);
    float4 q = make_float4(0.f, 0.f, 0.f, 0.f);
    for (int r = blockIdx.x * REPS + rep; r < n; r += gridDim.x * REPS) {
        float4 v = *(const float4*)(h + (size_t)r * D + ch4 * 4);
        s.x += v.x; s.y += v.y; s.z += v.z; s.w += v.w;
        q.x = fmaf(v.x, v.x, q.x); q.y = fmaf(v.y, v.y, q.y);
        q.z = fmaf(v.z, v.z, q.z); q.w = fmaf(v.w, v.w, q.w);
    }
    atomicAdd(&s_sum[ch4 * 4 + 0], s.x); atomicAdd(&s_sq[ch4 * 4 + 0], q.x);
    atomicAdd(&s_sum[ch4 * 4 + 1], s.y); atomicAdd(&s_sq[ch4 * 4 + 1], q.y);
    atomicAdd(&s_sum[ch4 * 4 + 2], s.z); atomicAdd(&s_sq[ch4 * 4 + 2], q.z);
    atomicAdd(&s_sum[ch4 * 4 + 3], s.w); atomicAdd(&s_sq[ch4 * 4 + 3], q.w);
    __syncthreads();
    if (tid < D) {
        atomicAdd(&g_stats[layer * 128 + tid], s_sum[tid]);
        atomicAdd(&g_stats[layer * 128 + 64 + tid], s_sq[tid]);
    }
}

// ---------------- persistent fused BN+ELU + small GEMM, fp16 output ----------
template <int IN, int OUT>
__global__ void __launch_bounds__(256) gemm_small_fused(
    const float* __restrict__ h, const float* __restrict__ W,
    const float* __restrict__ gamma, const float* __restrict__ beta,
    int layer, __half* __restrict__ out, int n) {
    __shared__ float Ws[IN * OUT];
    __shared__ float sc[IN], sh[IN];
    int tid = threadIdx.x;
    for (int i = tid; i < IN * OUT; i += blockDim.x) Ws[i] = W[i];
    if (tid < IN) {
        float invn = 1.0f / (float)n;
        float mean = g_stats[layer * 128 + tid] * invn;
        float var  = g_stats[layer * 128 + 64 + tid] * invn - mean * mean;
        float k    = rsqrtf(var + 1e-5f) * gamma[tid];
        sc[tid] = k;
        sh[tid] = beta[tid] - mean * k;
    }
    __syncthreads();
    int wid = tid >> 5, lane = tid & 31;
    for (int node = blockIdx.x * 8 + wid; node < n; node += gridDim.x * 8) {
        const float* hr = h + (size_t)node * IN;
        float acc0 = 0.f;
#pragma unroll
        for (int k = 0; k < IN; k += 4) {
            float4 h4 = *(const float4*)(hr + k);
            float y0 = fmaf(h4.x, sc[k + 0], sh[k + 0]);
            float y1 = fmaf(h4.y, sc[k + 1], sh[k + 1]);
            float y2 = fmaf(h4.z, sc[k + 2], sh[k + 2]);
            float y3 = fmaf(h4.w, sc[k + 3], sh[k + 3]);
            y0 = y0 > 0.f ? y0 : expm1f(y0);
            y1 = y1 > 0.f ? y1 : expm1f(y1);
            y2 = y2 > 0.f ? y2 : expm1f(y2);
            y3 = y3 > 0.f ? y3 : expm1f(y3);
            acc0 = fmaf(y0, Ws[(k + 0) * OUT + lane], acc0);
            acc0 = fmaf(y1, Ws[(k + 1) * OUT + lane], acc0);
            acc0 = fmaf(y2, Ws[(k + 2) * OUT + lane], acc0);
            acc0 = fmaf(y3, Ws[(k + 3) * OUT + lane], acc0);
        }
        if (lane < OUT) out[(size_t)node * OUT + lane] = __float2half_rn(acc0);
    }
}

// ---------------- standalone BN+ELU for D=16, fp16 output --------------------
__global__ void bn_elu16(const float* __restrict__ h, __half* __restrict__ out,
                         const float* __restrict__ gamma, const float* __restrict__ beta,
                         int n) {
    int i = blockIdx.x * blockDim.x + threadIdx.x;
    if (i >= n * 16) return;
    int ch = i & 15;
    float invn = 1.0f / (float)n;
    float mean = g_stats[256 + ch] * invn;
    float var  = g_stats[256 + 64 + ch] * invn - mean * mean;
    float k = rsqrtf(var + 1e-5f) * gamma[ch];
    float y = fmaf(h[i] - mean, k, beta[ch]);
    out[i] = __float2half_rn(y > 0.f ? y : expm1f(y));
}

// ---------------- final: [n,16]x[16,40] + log_softmax, persistent ------------
__global__ void __launch_bounds__(256) gemm40_lsm(
    const float* __restrict__ h, const float* __restrict__ W,
    float* __restrict__ out, int n) {
    __shared__ float Ws[16 * 40];
    int tid = threadIdx.x;
    for (int i = tid; i < 16 * 40; i += blockDim.x) Ws[i] = W[i];
    __syncthreads();
    int wid = tid >> 5, lane = tid & 31;
    for (int node = blockIdx.x * 8 + wid; node < n; node += gridDim.x * 8) {
        const float* hr = h + (size_t)node * 16;
        float acc0 = 0.f, acc1 = 0.f;
#pragma unroll
        for (int k = 0; k < 16; k += 4) {
            float4 h4 = *(const float4*)(hr + k);
            acc0 = fmaf(h4.x, Ws[(k + 0) * 40 + lane], acc0);
            acc0 = fmaf(h4.y, Ws[(k + 1) * 40 + lane], acc0);
            acc0 = fmaf(h4.z, Ws[(k + 2) * 40 + lane], acc0);
            acc0 = fmaf(h4.w, Ws[(k + 3) * 40 + lane], acc0);
            if (lane < 8) {
                acc1 = fmaf(h4.x, Ws[(k + 0) * 40 + 32 + lane], acc1);
                acc1 = fmaf(h4.y, Ws[(k + 1) * 40 + 32 + lane], acc1);
                acc1 = fmaf(h4.z, Ws[(k + 2) * 40 + 32 + lane], acc1);
                acc1 = fmaf(h4.w, Ws[(k + 3) * 40 + 32 + lane], acc1);
            }
        }
        float a1 = (lane < 8) ? acc1 : __int_as_float(0xff800000);
        float m = fmaxf(acc0, a1);
#pragma unroll
        for (int o = 16; o; o >>= 1) m = fmaxf(m, __shfl_xor_sync(0xffffffffu, m, o));
        float ssum = expf(acc0 - m) + ((lane < 8) ? expf(acc1 - m) : 0.f);
#pragma unroll
        for (int o = 16; o; o >>= 1) ssum += __shfl_xor_sync(0xffffffffu, ssum, o);
        float lse = logf(ssum) + m;
        out[(size_t)node * 40 + lane] = acc0 - lse;
        if (lane < 8) out[(size_t)node * 40 + 32 + lane] = acc1 - lse;
    }
}

// ---------------- launch ------------------------------------------------------
static inline int dg(long long t, int b) { return (int)((t + b - 1) / b); }

extern "C" void kernel_launch(void* const* d_in, const int* in_sizes, int n_in,
                              void* d_out, int out_size) {
    const float* x    = (const float*)d_in[0];
    const int*   erow = (const int*)d_in[1];
    const int*   ecol = (const int*)d_in[2];
    const float* ev   = (const float*)d_in[3];
    const float* W1   = (const float*)d_in[4];
    const float* W2   = (const float*)d_in[5];
    const float* W3   = (const float*)d_in[6];
    const float* W4   = (const float*)d_in[7];
    const float* g1   = (const float*)d_in[8];
    const float* b1   = (const float*)d_in[9];
    const float* g2   = (const float*)d_in[10];
    const float* b2   = (const float*)d_in[11];
    const float* g3   = (const float*)d_in[12];
    const float* b3   = (const float*)d_in[13];

    int n = in_sizes[0] / IN_DIM;
    int E = in_sizes[1];
    float* out = (float*)d_out;

    __half* hH; float* hF; int* rp;
    cudaGetSymbolAddress((void**)&hH, g_bufH);
    cudaGetSymbolAddress((void**)&hF, g_bufF);
    cudaGetSymbolAddress((void**)&rp, g_rp);

    const int TB = 256;
    const int PERS = 1184;
    const int STATS_BLOCKS = 592;

    build_rowptr<<<dg(n + 1, TB), TB>>>(erow, E, n, rp);

    // ---- layer 1 ----
    gemm1_kernel<<<dg(n, 256), 256>>>(x, W1, hH, n);
    spmm64h<<<dg((long long)n * 32, TB), TB>>>(hH, ecol, ev, rp, hF, n);
    col_stats<64><<<STATS_BLOCKS, 256>>>(hF, n, 0);

    // ---- layer 2 ----
    gemm_small_fused<64, 32><<<PERS, TB>>>(hF, W2, g1, b1, 0, hH, n);
    spmm32h<<<dg((long long)n * 32, TB), TB>>>(hH, ecol, ev, rp, hF, n);
    col_stats<32><<<STATS_BLOCKS, 256>>>(hF, n, 1);

    // ---- layer 3 ----
    gemm_small_fused<32, 16><<<PERS, TB>>>(hF, W3, g2, b2, 1, hH, n);
    spmm16h<<<dg((long long)n * 32, TB), TB>>>(hH, ecol, ev, rp, hF, n);
    col_stats<16><<<STATS_BLOCKS, 256>>>(hF, n, 2);

    // ---- layer 4 (commuted): bn+elu -> spmm16 -> gemm(16->40)+log_softmax ----
    bn_elu16<<<dg((long long)n * 16, TB), TB>>>(hF, hH, g3, b3, n);
    spmm16h<<<dg((long long)n * 32, TB), TB>>>(hH, ecol, ev, rp, hF, n);
    gemm40_lsm<<<PERS, TB>>>(hF, W4, out, n);
}

// round 9
// speedup vs baseline: 1.0691x; 1.0638x over previous
#include <cuda_runtime.h>
#include <cuda_fp16.h>
#include <cstdint>
#include <math.h>

#define MAXN 100000
#define IN_DIM 512

// ---------------- scratch ----------------------------------------------------
__device__ __half g_bufH[MAXN * 64];   // support matrices (gathered operand, fp16)
__device__ float  g_bufF[MAXN * 64];   // spmm outputs (fp32)
__device__ int    g_rp[MAXN + 1];
__device__ float  g_stats[384];        // 3 layers x (64 sum + 64 sumsq)

// ---------------- row_ptr (sorted edge_row) + full stats zeroing -------------
__global__ void build_rowptr(const int* __restrict__ erow, int E, int n, int* __restrict__ rp) {
    if (blockIdx.x == 0) {
        for (int k = threadIdx.x; k < 384; k += blockDim.x) g_stats[k] = 0.f;
    }
    int i = blockIdx.x * blockDim.x + threadIdx.x;
    if (i > n) return;
    int lo = 0, hi = E;
    while (lo < hi) { int mid = (lo + hi) >> 1; if (erow[mid] < i) lo = mid + 1; else hi = mid; }
    rp[i] = lo;
}

// ---------------- HMMA m16n8k16 fp16 -> fp32 ---------------------------------
__device__ __forceinline__ void mma16816(float* c, uint32_t a0, uint32_t a1,
                                         uint32_t a2, uint32_t a3,
                                         uint32_t b0, uint32_t b1) {
    asm volatile(
        "mma.sync.aligned.m16n8k16.row.col.f32.f16.f16.f32 "
        "{%0,%1,%2,%3}, {%4,%5,%6,%7}, {%8,%9}, {%0,%1,%2,%3};"
        : "+f"(c[0]), "+f"(c[1]), "+f"(c[2]), "+f"(c[3])
        : "r"(a0), "r"(a1), "r"(a2), "r"(a3), "r"(b0), "r"(b1));
}

// ---------------- GEMM1: [M,512]x[512,64] via HMMA, A split hi+lo ------------
// Block: 128 rows x 64 cols, 8 warps (4m x 2n), K chunked by 64.
__global__ void __launch_bounds__(256, 4) gemm1_hmma(
    const float* __restrict__ A, const float* __restrict__ B,
    __half* __restrict__ C, int M) {
    __shared__ __half sAhi[128][72];
    __shared__ __half sAlo[128][72];
    __shared__ __half sB[64][72];      // transposed: [n][k]

    int tid = threadIdx.x;
    int wid = tid >> 5, lane = tid & 31;
    int wm = wid & 3, wn = wid >> 2;
    int rowBase = blockIdx.x * 128;
    int r = lane >> 2;                 // groupID 0..7
    int cq = (lane & 3) * 2;           // 2*tig: 0,2,4,6

    float acc[2][4][4];
#pragma unroll
    for (int mt = 0; mt < 2; ++mt)
#pragma unroll
        for (int nt = 0; nt < 4; ++nt)
#pragma unroll
            for (int i = 0; i < 4; ++i) acc[mt][nt][i] = 0.f;

    for (int kt = 0; kt < 512; kt += 64) {
        // load A chunk: 128 rows x 64 k (fp32 -> hi/lo fp16)
#pragma unroll
        for (int i = 0; i < 8; ++i) {
            int idx = tid + i * 256;
            int row = idx >> 4, c4 = (idx & 15) * 4;
            int grow = rowBase + row;
            float4 v = make_float4(0.f, 0.f, 0.f, 0.f);
            if (grow < M) v = *(const float4*)(A + (size_t)grow * 512 + kt + c4);
            __half h0 = __float2half_rn(v.x), h1 = __float2half_rn(v.y);
            __half h2 = __float2half_rn(v.z), h3 = __float2half_rn(v.w);
            __half2 hi01 = __halves2half2(h0, h1), hi23 = __halves2half2(h2, h3);
            __half2 lo01 = __floats2half2_rn(v.x - __half2float(h0), v.y - __half2float(h1));
            __half2 lo23 = __floats2half2_rn(v.z - __half2float(h2), v.w - __half2float(h3));
            *(__half2*)&sAhi[row][c4]     = hi01;
            *(__half2*)&sAhi[row][c4 + 2] = hi23;
            *(__half2*)&sAlo[row][c4]     = lo01;
            *(__half2*)&sAlo[row][c4 + 2] = lo23;
        }
        // load B chunk transposed: B[kt+k][n] -> sB[n][k]  (FULL 64 k rows)
#pragma unroll
        for (int i = 0; i < 4; ++i) {
            int idx = tid + i * 256;
            int k = idx >> 4, n4 = (idx & 15) * 4;
            float4 v = *(const float4*)(B + (size_t)(kt + k) * 64 + n4);
            sB[n4 + 0][k] = __float2half_rn(v.x);
            sB[n4 + 1][k] = __float2half_rn(v.y);
            sB[n4 + 2][k] = __float2half_rn(v.z);
            sB[n4 + 3][k] = __float2half_rn(v.w);
        }
        __syncthreads();

#pragma unroll
        for (int ks = 0; ks < 4; ++ks) {
            int c = cq + ks * 16;
            uint32_t bh[4][2];
#pragma unroll
            for (int nt = 0; nt < 4; ++nt) {
                int col = wn * 32 + nt * 8 + r;
                bh[nt][0] = *(const uint32_t*)&sB[col][c];
                bh[nt][1] = *(const uint32_t*)&sB[col][c + 8];
            }
#pragma unroll
            for (int mt = 0; mt < 2; ++mt) {
                int m = wm * 32 + mt * 16;
                uint32_t ah0 = *(const uint32_t*)&sAhi[m + r][c];
                uint32_t ah1 = *(const uint32_t*)&sAhi[m + r + 8][c];
                uint32_t ah2 = *(const uint32_t*)&sAhi[m + r][c + 8];
                uint32_t ah3 = *(const uint32_t*)&sAhi[m + r + 8][c + 8];
                uint32_t al0 = *(const uint32_t*)&sAlo[m + r][c];
                uint32_t al1 = *(const uint32_t*)&sAlo[m + r + 8][c];
                uint32_t al2 = *(const uint32_t*)&sAlo[m + r][c + 8];
                uint32_t al3 = *(const uint32_t*)&sAlo[m + r + 8][c + 8];
#pragma unroll
                for (int nt = 0; nt < 4; ++nt) {
                    mma16816(acc[mt][nt], ah0, ah1, ah2, ah3, bh[nt][0], bh[nt][1]);
                    mma16816(acc[mt][nt], al0, al1, al2, al3, bh[nt][0], bh[nt][1]);
                }
            }
        }
        __syncthreads();
    }

    // epilogue: fp16 output
#pragma unroll
    for (int mt = 0; mt < 2; ++mt) {
        int row0 = rowBase + wm * 32 + mt * 16 + r;
        int row1 = row0 + 8;
#pragma unroll
        for (int nt = 0; nt < 4; ++nt) {
            int col = wn * 32 + nt * 8 + cq;
            if (row0 < M)
                *(__half2*)(C + (size_t)row0 * 64 + col) =
                    __floats2half2_rn(acc[mt][nt][0], acc[mt][nt][1]);
            if (row1 < M)
                *(__half2*)(C + (size_t)row1 * 64 + col) =
                    __floats2half2_rn(acc[mt][nt][2], acc[mt][nt][3]);
        }
    }
}

// ---------------- fp16 gather helper ----------------------------------------
__device__ __forceinline__ void fma_half8(float* acc, uint4 raw, float v) {
    float2 f;
    f = __half22float2(*(__half2*)&raw.x); acc[0] = fmaf(v, f.x, acc[0]); acc[1] = fmaf(v, f.y, acc[1]);
    f = __half22float2(*(((__half2*)&raw.x) + 1)); acc[2] = fmaf(v, f.x, acc[2]); acc[3] = fmaf(v, f.y, acc[3]);
    f = __half22float2(*(__half2*)&raw.z); acc[4] = fmaf(v, f.x, acc[4]); acc[5] = fmaf(v, f.y, acc[5]);
    f = __half22float2(*(((__half2*)&raw.z) + 1)); acc[6] = fmaf(v, f.x, acc[6]); acc[7] = fmaf(v, f.y, acc[7]);
}

// ---------------- SpMM: half supports, float outputs -------------------------
__global__ void __launch_bounds__(256) spmm64h(
    const __half* __restrict__ sup, const int* __restrict__ ecol,
    const float* __restrict__ ev, const int* __restrict__ rp,
    float* __restrict__ out, int n) {
    int gw = (blockIdx.x * blockDim.x + threadIdx.x) >> 5;
    int lane = threadIdx.x & 31;
    if (gw >= n) return;
    int s = rp[gw], e = rp[gw + 1];
    int g = lane >> 3, sl = lane & 7;
    float acc[8] = {0.f, 0.f, 0.f, 0.f, 0.f, 0.f, 0.f, 0.f};
    for (int j = s + g; j < e; j += 4) {
        int c = ecol[j]; float v = ev[j];
        uint4 raw = *(const uint4*)(sup + (size_t)c * 64 + sl * 8);
        fma_half8(acc, raw, v);
    }
#pragma unroll
    for (int o = 16; o >= 8; o >>= 1)
#pragma unroll
        for (int i = 0; i < 8; ++i) acc[i] += __shfl_down_sync(0xffffffffu, acc[i], o);
    if (lane < 8) {
        float* op = out + (size_t)gw * 64 + lane * 8;
        *(float4*)op       = make_float4(acc[0], acc[1], acc[2], acc[3]);
        *(float4*)(op + 4) = make_float4(acc[4], acc[5], acc[6], acc[7]);
    }
}

__global__ void __launch_bounds__(256) spmm32h(
    const __half* __restrict__ sup, const int* __restrict__ ecol,
    const float* __restrict__ ev, const int* __restrict__ rp,
    float* __restrict__ out, int n) {
    int gw = (blockIdx.x * blockDim.x + threadIdx.x) >> 5;
    int lane = threadIdx.x & 31;
    if (gw >= n) return;
    int s = rp[gw], e = rp[gw + 1];
    int g = lane >> 2, sl = lane & 3;
    float acc[8] = {0.f, 0.f, 0.f, 0.f, 0.f, 0.f, 0.f, 0.f};
    for (int j = s + g; j < e; j += 8) {
        int c = ecol[j]; float v = ev[j];
        uint4 raw = *(const uint4*)(sup + (size_t)c * 32 + sl * 8);
        fma_half8(acc, raw, v);
    }
#pragma unroll
    for (int o = 16; o >= 4; o >>= 1)
#pragma unroll
        for (int i = 0; i < 8; ++i) acc[i] += __shfl_down_sync(0xffffffffu, acc[i], o);
    if (lane < 4) {
        float* op = out + (size_t)gw * 32 + lane * 8;
        *(float4*)op       = make_float4(acc[0], acc[1], acc[2], acc[3]);
        *(float4*)(op + 4) = make_float4(acc[4], acc[5], acc[6], acc[7]);
    }
}

__global__ void __launch_bounds__(256) spmm16h(
    const __half* __restrict__ sup, const int* __restrict__ ecol,
    const float* __restrict__ ev, const int* __restrict__ rp,
    float* __restrict__ out, int n) {
    int gw = (blockIdx.x * blockDim.x + threadIdx.x) >> 5;
    int lane = threadIdx.x & 31;
    if (gw >= n) return;
    int s = rp[gw], e = rp[gw + 1];
    int g = lane >> 1, sl = lane & 1;
    float acc[8] = {0.f, 0.f, 0.f, 0.f, 0.f, 0.f, 0.f, 0.f};
    for (int j = s + g; j < e; j += 16) {
        int c = ecol[j]; float v = ev[j];
        uint4 raw = *(const uint4*)(sup + (size_t)c * 16 + sl * 8);
        fma_half8(acc, raw, v);
    }
#pragma unroll
    for (int o = 16; o >= 2; o >>= 1)
#pragma unroll
        for (int i = 0; i < 8; ++i) acc[i] += __shfl_down_sync(0xffffffffu, acc[i], o);
    if (lane < 2) {
        float* op = out + (size_t)gw * 16 + lane * 8;
        *(float4*)op       = make_float4(acc[0], acc[1], acc[2], acc[3]);
        *(float4*)(op + 4) = make_float4(acc[4], acc[5], acc[6], acc[7]);
    }
}

// ---------------- column stats: float4 reads, one flush per block ------------
template <int D>
__global__ void __launch_bounds__(256) col_stats(const float* __restrict__ h, int n, int layer) {
    const int S4 = D / 4;
    const int REPS = 256 / S4;
    __shared__ float s_sum[D], s_sq[D];
    int tid = threadIdx.x;
    if (tid < D) { s_sum[tid] = 0.f; s_sq[tid] = 0.f; }
    __syncthreads();
    int ch4 = tid % S4, rep = tid / S4;
    float4 s = make_float4(0.f, 0.f, 0.f, 0.f);
    float4 q = make_float4(0.f, 0.f, 0.f, 0.f);
    for (int r = blockIdx.x * REPS + rep; r < n; r += gridDim.x * REPS) {
        float4 v = *(const float4*)(h + (size_t)r * D + ch4 * 4);
        s.x += v.x; s.y += v.y; s.z += v.z; s.w += v.w;
        q.x = fmaf(v.x, v.x, q.x); q.y = fmaf(v.y, v.y, q.y);
        q.z = fmaf(v.z, v.z, q.z); q.w = fmaf(v.w, v.w, q.w);
    }
    atomicAdd(&s_sum[ch4 * 4 + 0], s.x); atomicAdd(&s_sq[ch4 * 4 + 0], q.x);
    atomicAdd(&s_sum[ch4 * 4 + 1], s.y); atomicAdd(&s_sq[ch4 * 4 + 1], q.y);
    atomicAdd(&s_sum[ch4 * 4 + 2], s.z); atomicAdd(&s_sq[ch4 * 4 + 2], q.z);
    atomicAdd(&s_sum[ch4 * 4 + 3], s.w); atomicAdd(&s_sq[ch4 * 4 + 3], q.w);
    __syncthreads();
    if (tid < D) {
        atomicAdd(&g_stats[layer * 128 + tid], s_sum[tid]);
        atomicAdd(&g_stats[layer * 128 + 64 + tid], s_sq[tid]);
    }
}

// ---------------- persistent fused BN+ELU + small GEMM, fp16 output ----------
template <int IN, int OUT>
__global__ void __launch_bounds__(256) gemm_small_fused(
    const float* __restrict__ h, const float* __restrict__ W,
    const float* __restrict__ gamma, const float* __restrict__ beta,
    int layer, __half* __restrict__ out, int n) {
    __shared__ float Ws[IN * OUT];
    __shared__ float sc[IN], sh[IN];
    int tid = threadIdx.x;
    for (int i = tid; i < IN * OUT; i += blockDim.x) Ws[i] = W[i];
    if (tid < IN) {
        float invn = 1.0f / (float)n;
        float mean = g_stats[layer * 128 + tid] * invn;
        float var  = g_stats[layer * 128 + 64 + tid] * invn - mean * mean;
        float k    = rsqrtf(var + 1e-5f) * gamma[tid];
        sc[tid] = k;
        sh[tid] = beta[tid] - mean * k;
    }
    __syncthreads();
    int wid = tid >> 5, lane = tid & 31;
    for (int node = blockIdx.x * 8 + wid; node < n; node += gridDim.x * 8) {
        const float* hr = h + (size_t)node * IN;
        float acc0 = 0.f;
#pragma unroll
        for (int k = 0; k < IN; k += 4) {
            float4 h4 = *(const float4*)(hr + k);
            float y0 = fmaf(h4.x, sc[k + 0], sh[k + 0]);
            float y1 = fmaf(h4.y, sc[k + 1], sh[k + 1]);
            float y2 = fmaf(h4.z, sc[k + 2], sh[k + 2]);
            float y3 = fmaf(h4.w, sc[k + 3], sh[k + 3]);
            y0 = y0 > 0.f ? y0 : expm1f(y0);
            y1 = y1 > 0.f ? y1 : expm1f(y1);
            y2 = y2 > 0.f ? y2 : expm1f(y2);
            y3 = y3 > 0.f ? y3 : expm1f(y3);
            acc0 = fmaf(y0, Ws[(k + 0) * OUT + lane], acc0);
            acc0 = fmaf(y1, Ws[(k + 1) * OUT + lane], acc0);
            acc0 = fmaf(y2, Ws[(k + 2) * OUT + lane], acc0);
            acc0 = fmaf(y3, Ws[(k + 3) * OUT + lane], acc0);
        }
        if (lane < OUT) out[(size_t)node * OUT + lane] = __float2half_rn(acc0);
    }
}

// ---------------- standalone BN+ELU for D=16, fp16 output --------------------
__global__ void bn_elu16(const float* __restrict__ h, __half* __restrict__ out,
                         const float* __restrict__ gamma, const float* __restrict__ beta,
                         int n) {
    int i = blockIdx.x * blockDim.x + threadIdx.x;
    if (i >= n * 16) return;
    int ch = i & 15;
    float invn = 1.0f / (float)n;
    float mean = g_stats[256 + ch] * invn;
    float var  = g_stats[256 + 64 + ch] * invn - mean * mean;
    float k = rsqrtf(var + 1e-5f) * gamma[ch];
    float y = fmaf(h[i] - mean, k, beta[ch]);
    out[i] = __float2half_rn(y > 0.f ? y : expm1f(y));
}

// ---------------- final: [n,16]x[16,40] + log_softmax, persistent ------------
__global__ void __launch_bounds__(256) gemm40_lsm(
    const float* __restrict__ h, const float* __restrict__ W,
    float* __restrict__ out, int n) {
    __shared__ float Ws[16 * 40];
    int tid = threadIdx.x;
    for (int i = tid; i < 16 * 40; i += blockDim.x) Ws[i] = W[i];
    __syncthreads();
    int wid = tid >> 5, lane = tid & 31;
    for (int node = blockIdx.x * 8 + wid; node < n; node += gridDim.x * 8) {
        const float* hr = h + (size_t)node * 16;
        float acc0 = 0.f, acc1 = 0.f;
#pragma unroll
        for (int k = 0; k < 16; k += 4) {
            float4 h4 = *(const float4*)(hr + k);
            acc0 = fmaf(h4.x, Ws[(k + 0) * 40 + lane], acc0);
            acc0 = fmaf(h4.y, Ws[(k + 1) * 40 + lane], acc0);
            acc0 = fmaf(h4.z, Ws[(k + 2) * 40 + lane], acc0);
            acc0 = fmaf(h4.w, Ws[(k + 3) * 40 + lane], acc0);
            if (lane < 8) {
                acc1 = fmaf(h4.x, Ws[(k + 0) * 40 + 32 + lane], acc1);
                acc1 = fmaf(h4.y, Ws[(k + 1) * 40 + 32 + lane], acc1);
                acc1 = fmaf(h4.z, Ws[(k + 2) * 40 + 32 + lane], acc1);
                acc1 = fmaf(h4.w, Ws[(k + 3) * 40 + 32 + lane], acc1);
            }
        }
        float a1 = (lane < 8) ? acc1 : __int_as_float(0xff800000);
        float m = fmaxf(acc0, a1);
#pragma unroll
        for (int o = 16; o; o >>= 1) m = fmaxf(m, __shfl_xor_sync(0xffffffffu, m, o));
        float ssum = expf(acc0 - m) + ((lane < 8) ? expf(acc1 - m) : 0.f);
#pragma unroll
        for (int o = 16; o; o >>= 1) ssum += __shfl_xor_sync(0xffffffffu, ssum, o);
        float lse = logf(ssum) + m;
        out[(size_t)node * 40 + lane] = acc0 - lse;
        if (lane < 8) out[(size_t)node * 40 + 32 + lane] = acc1 - lse;
    }
}

// ---------------- launch ------------------------------------------------------
static inline int dg(long long t, int b) { return (int)((t + b - 1) / b); }

extern "C" void kernel_launch(void* const* d_in, const int* in_sizes, int n_in,
                              void* d_out, int out_size) {
    const float* x    = (const float*)d_in[0];
    const int*   erow = (const int*)d_in[1];
    const int*   ecol = (const int*)d_in[2];
    const float* ev   = (const float*)d_in[3];
    const float* W1   = (const float*)d_in[4];
    const float* W2   = (const float*)d_in[5];
    const float* W3   = (const float*)d_in[6];
    const float* W4   = (const float*)d_in[7];
    const float* g1   = (const float*)d_in[8];
    const float* b1   = (const float*)d_in[9];
    const float* g2   = (const float*)d_in[10];
    const float* b2   = (const float*)d_in[11];
    const float* g3   = (const float*)d_in[12];
    const float* b3   = (const float*)d_in[13];

    int n = in_sizes[0] / IN_DIM;
    int E = in_sizes[1];
    float* out = (float*)d_out;

    __half* hH; float* hF; int* rp;
    cudaGetSymbolAddress((void**)&hH, g_bufH);
    cudaGetSymbolAddress((void**)&hF, g_bufF);
    cudaGetSymbolAddress((void**)&rp, g_rp);

    const int TB = 256;
    const int PERS = 1184;
    const int STATS_BLOCKS = 592;

    build_rowptr<<<dg(n + 1, TB), TB>>>(erow, E, n, rp);

    // ---- layer 1: HMMA gemm -> spmm64 -> stats ----
    gemm1_hmma<<<dg(n, 128), 256>>>(x, W1, hH, n);
    spmm64h<<<dg((long long)n * 32, TB), TB>>>(hH, ecol, ev, rp, hF, n);
    col_stats<64><<<STATS_BLOCKS, 256>>>(hF, n, 0);

    // ---- layer 2 ----
    gemm_small_fused<64, 32><<<PERS, TB>>>(hF, W2, g1, b1, 0, hH, n);
    spmm32h<<<dg((long long)n * 32, TB), TB>>>(hH, ecol, ev, rp, hF, n);
    col_stats<32><<<STATS_BLOCKS, 256>>>(hF, n, 1);

    // ---- layer 3 ----
    gemm_small_fused<32, 16><<<PERS, TB>>>(hF, W3, g2, b2, 1, hH, n);
    spmm16h<<<dg((long long)n * 32, TB), TB>>>(hH, ecol, ev, rp, hF, n);
    col_stats<16><<<STATS_BLOCKS, 256>>>(hF, n, 2);

    // ---- layer 4 (commuted): bn+elu -> spmm16 -> gemm(16->40)+log_softmax ----
    bn_elu16<<<dg((long long)n * 16, TB), TB>>>(hF, hH, g3, b3, n);
    spmm16h<<<dg((long long)n * 32, TB), TB>>>(hH, ecol, ev, rp, hF, n);
    gemm40_lsm<<<PERS, TB>>>(hF, W4, out, n);
}